// round 11
// baseline (speedup 1.0000x reference)
#include <cuda_runtime.h>
#include <cuda_bf16.h>
#include <math.h>

// Problem constants (fixed by setup_inputs)
#define B_N 4096
#define M_N 256
#define D_N 256

#define TAU_INV_LOG2E 7.213475204444817f   // log2(e)/0.2
#define LAM_INV_LOG2E 0.18033688011112043f // log2(e)/8
#define TOPO_C 0.5f
#define LEN_C 0.01f
#define SP_C 0.001f

typedef unsigned long long u64;

// ---------------- packed f32x2 helpers (sm_103a) ----------------
__device__ __forceinline__ u64 f2add(u64 a, u64 b) {
    u64 o; asm("add.rn.f32x2 %0, %1, %2;" : "=l"(o) : "l"(a), "l"(b)); return o;
}
__device__ __forceinline__ u64 f2mul(u64 a, u64 b) {
    u64 o; asm("mul.rn.f32x2 %0, %1, %2;" : "=l"(o) : "l"(a), "l"(b)); return o;
}
__device__ __forceinline__ u64 f2fma(u64 a, u64 b, u64 c) {
    u64 o; asm("fma.rn.f32x2 %0, %1, %2, %3;" : "=l"(o) : "l"(a), "l"(b), "l"(c)); return o;
}
__device__ __forceinline__ u64 f2dup(float x) {
    u64 o; asm("mov.b64 %0, {%1, %1};" : "=l"(o) : "f"(x)); return o;
}
__device__ __forceinline__ u64 f2pack(float x, float y) {
    u64 o; asm("mov.b64 %0, {%1, %2};" : "=l"(o) : "f"(x), "f"(y)); return o;
}
__device__ __forceinline__ float2 f2unpack(u64 v) {
    float2 o; asm("mov.b64 {%0, %1}, %2;" : "=f"(o.x), "=f"(o.y) : "l"(v)); return o;
}
__device__ __forceinline__ float frcp(float x) {
    float r; asm("rcp.approx.ftz.f32 %0, %1;" : "=f"(r) : "f"(x)); return r;
}

// ---------------- device scratch (no allocations allowed) ----------------
__device__ float g_Wtp[128 * 512];        // W transposed, k-pair-major: [k2][m][2], 256KB
__device__ float g_dist[B_N * M_N];       // 4 MB (L2-resident)
__device__ float g_dmax[B_N];             // per-row max distance
__device__ float g_wsq[M_N];
__device__ float g_factor[M_N];
__device__ float g_ep_rowsum[M_N];
__device__ float g_wl_rowsum[M_N];
__device__ float g_part[B_N];
__device__ unsigned int g_ctr = 0u;       // rank ticket (winner resets)
__device__ unsigned int g_wtp_ready = 0u; // wprep completion count (winner resets)

// acquire-wait for all 16 wprep blocks (called by every edges/gemm block)
__device__ __forceinline__ void wait_wtp() {
    if (threadIdx.x == 0) {
        while (atomicAdd(&g_wtp_ready, 0u) < 16u) __nanosleep(128);
        __threadfence();
    }
    __syncthreads();
}

// ---------------- K1 "produce": wprep (0..15) + edges (16..47) + GEMM (48..303) ----------------
__global__ void __launch_bounds__(256) k_produce(const float* __restrict__ X,
                                                 const float* __restrict__ W,
                                                 const float* __restrict__ E) {
    const int t = threadIdx.x;
    const int lane = t & 31, warp = t >> 5;
    const int bid = blockIdx.x;

    __shared__ __align__(16) float sm[8192];   // 32KB carved per branch

    if (bid < 16) {
        // ============ WPREP: wsq + transpose of 16 W rows ============
        float (*Ws)[260] = (float (*)[260])sm;   // 4160 floats
        const int m0 = bid * 16;
#pragma unroll
        for (int p = 0; p < 16; p++) {
            int q = t + p * 256;
            int r = q >> 8, k = q & 255;
            Ws[r][k] = W[(size_t)(m0 + r) * D_N + k];
        }
        __syncthreads();

#pragma unroll
        for (int rr = 0; rr < 2; rr++) {
            int row = warp * 2 + rr;
            float s = 0.0f;
#pragma unroll
            for (int p = 0; p < 8; p++) {
                float v = Ws[row][lane + 32 * p];
                s = fmaf(v, v, s);
            }
#pragma unroll
            for (int o = 16; o; o >>= 1) s += __shfl_xor_sync(0xffffffffu, s, o);
            if (lane == 0) g_wsq[m0 + row] = s;
        }

#pragma unroll
        for (int p = 0; p < 16; p++) {
            int k2 = p * 8 + warp;       // 0..127
            int mloc = lane >> 1, e = lane & 1;
            g_Wtp[k2 * 512 + (m0 + mloc) * 2 + e] = Ws[mloc][k2 * 2 + e];
        }

        // release: all writes visible, then signal
        __threadfence();
        __syncthreads();
        if (t == 0) atomicAdd(&g_wtp_ready, 1u);
        return;
    }

    if (bid < 48) {
        // ============ EDGES: 8 i-rows per block, 1 j-column per thread ============
        const int i0 = (bid - 16) * 8;
        float* wis = sm;                 // 8 x 256
        float* red_ep = sm + 2048;       // [8][8]
        float* red_wl = sm + 2112;       // [8][8]

#pragma unroll
        for (int p = 0; p < 8; p++) {
            int q = t + p * 256;
            int r = q >> 8, k = q & 255;
            wis[r * 256 + k] = W[(size_t)(i0 + r) * D_N + k];
        }
        wait_wtp();   // also covers the wis writes via its barrier

        u64 acc[8];
#pragma unroll
        for (int i = 0; i < 8; i++) acc[i] = 0ull;

        const float* wtpj = g_Wtp + t * 2;
#pragma unroll 4
        for (int k2 = 0; k2 < 128; k2++) {
            u64 wj = *(const u64*)(wtpj + k2 * 512);
#pragma unroll
            for (int i = 0; i < 8; i++)
                acc[i] = f2fma(*(const u64*)&wis[i * 256 + 2 * k2], wj, acc[i]);
        }

        float wsqj = g_wsq[t];
#pragma unroll
        for (int i = 0; i < 8; i++) {
            int ig = i0 + i;
            float2 q = f2unpack(acc[i]);
            float dot = q.x + q.y;
            float pd = fmaxf(g_wsq[ig] + wsqj - 2.0f * dot, 0.0f);

            float lij = 0.5f * (E[ig * M_N + t] + E[t * M_N + ig]);
            float ep = __fdividef(1.0f, 1.0f + __expf(-lij));
            if (t == ig) ep = 0.0f;

            float sep = ep, swl = ep * pd;
#pragma unroll
            for (int o = 16; o; o >>= 1) {
                sep += __shfl_xor_sync(0xffffffffu, sep, o);
                swl += __shfl_xor_sync(0xffffffffu, swl, o);
            }
            if (lane == 0) { red_ep[i * 8 + warp] = sep; red_wl[i * 8 + warp] = swl; }
        }
        __syncthreads();
        if (t < 8) {
            float rs = 0.0f, rw = 0.0f;
#pragma unroll
            for (int w = 0; w < 8; w++) { rs += red_ep[t * 8 + w]; rw += red_wl[t * 8 + w]; }
            int ig = i0 + t;
            g_ep_rowsum[ig] = rs;
            g_wl_rowsum[ig] = rw;
            g_factor[ig] = 1.0f + TOPO_C * (rs / (float)(M_N - 1));
        }
        return;
    }

    // ============ GEMM: 16 data rows per block, 1 m-column per thread ============
    {
        const int b0 = (bid - 48) * 16;
        float* Xs = sm;                  // [16][256]
        float* pool = sm + 4096;         // 4096 floats: W chunk (8 k2-rows)

        // load X tile first (overlaps the wprep wait)
#pragma unroll
        for (int p = 0; p < 4; p++) {
            int q = t + p * 256;         // float4 idx 0..1023
            int r = q >> 6, c4 = q & 63;
            *(float4*)&Xs[r * 256 + c4 * 4] = ((const float4*)X)[(size_t)(b0 + r) * 64 + c4];
        }
        wait_wtp();   // barrier also publishes Xs

        u64 acc[16];
#pragma unroll
        for (int r = 0; r < 16; r++) acc[r] = 0ull;

        for (int chunk = 0; chunk < 16; chunk++) {
            const float4* src = (const float4*)(g_Wtp + chunk * 4096);
#pragma unroll
            for (int p = 0; p < 4; p++) {
                int idx = t + p * 256;
                ((float4*)pool)[idx] = src[idx];
            }
            __syncthreads();

#pragma unroll
            for (int k2p = 0; k2p < 4; k2p++) {
                int k2 = 2 * k2p;
                u64 w0 = *(const u64*)&pool[k2 * 512 + t * 2];
                u64 w1 = *(const u64*)&pool[(k2 + 1) * 512 + t * 2];
                int kg = chunk * 16 + k2p * 4;       // float idx into Xs row, 16B aligned
#pragma unroll
                for (int r = 0; r < 16; r++) {
                    ulonglong2 xv = *(const ulonglong2*)&Xs[r * 256 + kg];  // broadcast
                    acc[r] = f2fma(xv.x, w0, acc[r]);
                    acc[r] = f2fma(xv.y, w1, acc[r]);
                }
            }
            __syncthreads();
        }

        // xsq per row (warp w -> rows 2w, 2w+1), into pool[0..15]
#pragma unroll
        for (int rr = 0; rr < 2; rr++) {
            int row = warp * 2 + rr;
            float s = 0.0f;
#pragma unroll
            for (int p = 0; p < 8; p++) {
                float v = Xs[row * 256 + lane + 32 * p];
                s = fmaf(v, v, s);
            }
#pragma unroll
            for (int o = 16; o; o >>= 1) s += __shfl_xor_sync(0xffffffffu, s, o);
            if (lane == 0) pool[row] = s;
        }
        __syncthreads();

        float wsqt = g_wsq[t];
#pragma unroll
        for (int r = 0; r < 16; r++) {
            float2 dd = f2unpack(acc[r]);
            float dot = dd.x + dd.y;
            float d = sqrtf(fmaxf(pool[r] + wsqt - 2.0f * dot, 0.0f));
            g_dist[(size_t)(b0 + r) * M_N + t] = d;
            // row max across the block (scratch at pool[64..191])
            float mx = d;
#pragma unroll
            for (int o = 16; o; o >>= 1) mx = fmaxf(mx, __shfl_xor_sync(0xffffffffu, mx, o));
            if (lane == 0) pool[64 + r * 8 + warp] = mx;
        }
        __syncthreads();
        if (t < 16) {
            float m = pool[64 + t * 8];
#pragma unroll
            for (int w = 1; w < 8; w++) m = fmaxf(m, pool[64 + t * 8 + w]);
            g_dmax[b0 + t] = m;
        }
    }
}

// ---------------- K2: soft-rank via quartic + synthetic-division derivative ----------------
__global__ void __launch_bounds__(256) k_rank(float* __restrict__ out) {
    const int b = blockIdx.x;
    const int t = threadIdx.x;
    const int lane = t & 31, warp = t >> 5;

    __shared__ __align__(16) float us[256];        // interleaved u table (128 u64 pairs)
    __shared__ __align__(16) ulonglong2 tbl[64];   // 32 groups x {e1,e2},{e3,e4}
    __shared__ float red[8];

    float d = g_dist[(size_t)b * M_N + t];
    float dmax = __ldg(&g_dmax[b]);

    // u table (rescaled by 2^30; ratio-invariant). P in [2^-120, 2^124]: safe.
    float arg = fmaxf((d - dmax) * TAU_INV_LOG2E, -60.0f) + 30.0f;
    float ui = exp2f(arg);
    us[2 * (t & 127) + (t >> 7)] = ui;   // u64 slot k = (u_k, u_{k+128})
    __syncthreads();

    // build per-group coefficient tables (32 groups of 4 packed u's)
    if (t < 32) {
        const u64* uv = (const u64*)us;
        u64 u0 = uv[4 * t], u1 = uv[4 * t + 1], u2 = uv[4 * t + 2], u3 = uv[4 * t + 3];
        u64 s01 = f2add(u0, u1), p01 = f2mul(u0, u1);
        u64 s23 = f2add(u2, u3), p23 = f2mul(u2, u3);
        ulonglong2 A, Bc;
        A.x = f2add(s01, s23);                       // e1
        A.y = f2fma(s01, s23, f2add(p01, p23));      // e2
        Bc.x = f2fma(p01, s23, f2mul(p23, s01));     // e3
        Bc.y = f2mul(p01, p23);                      // e4
        tbl[2 * t] = A; tbl[2 * t + 1] = Bc;
    }
    __syncthreads();

    const u64 ui2 = f2dup(ui);
    u64 acc = 0ull;
#pragma unroll 8
    for (int g = 0; g < 32; g++) {
        ulonglong2 A = tbl[2 * g];         // e1, e2
        ulonglong2 Bc = tbl[2 * g + 1];    // e3, e4
        // P Horner with intermediates
        u64 t1 = f2add(ui2, A.x);
        u64 t2 = f2fma(t1, ui2, A.y);
        u64 t3 = f2fma(t2, ui2, Bc.x);
        u64 P  = f2fma(t3, ui2, Bc.y);
        // P' = ((x + t1)x + t2)x + t3  (synthetic division)
        u64 q1 = f2add(ui2, t1);
        u64 q2 = f2fma(q1, ui2, t2);
        u64 Dv = f2fma(q2, ui2, t3);
        // rcp + accumulate P'/P
        float2 pu = f2unpack(P);
        u64 rr = f2pack(frcp(pu.x), frcp(pu.y));
        acc = f2fma(Dv, rr, acc);
    }
    float2 av = f2unpack(acc);
    float ssum = ui * (av.x + av.y);       // includes diagonal 0.5
    float neigh = exp2f(-(ssum - 0.5f) * LAM_INV_LOG2E);
    float contrib = neigh * d * g_factor[t];

#pragma unroll
    for (int o = 16; o; o >>= 1) contrib += __shfl_xor_sync(0xffffffffu, contrib, o);
    if (lane == 0) red[warp] = contrib;
    __syncthreads();
    if (t == 0) {
        float s = red[0];
#pragma unroll
        for (int w = 1; w < 8; w++) s += red[w];
        g_part[b] = s;
    }

    // ---- last block: final loss assembly + flag reset for next replay ----
    __shared__ unsigned int ticket;
    __threadfence();
    __syncthreads();
    if (t == 0) ticket = atomicAdd(&g_ctr, 1u);
    __syncthreads();
    if (ticket != (unsigned int)(gridDim.x - 1)) return;

    __shared__ float fin[24];
    float sd = 0.0f;
    const float4* gp4 = (const float4*)g_part;
#pragma unroll
    for (int p = 0; p < 4; p++) {
        float4 v = gp4[t + 256 * p];
        sd += (v.x + v.y) + (v.z + v.w);
    }
    float se = g_ep_rowsum[t];
    float sw = g_wl_rowsum[t];
#pragma unroll
    for (int o = 16; o; o >>= 1) {
        sd += __shfl_xor_sync(0xffffffffu, sd, o);
        se += __shfl_xor_sync(0xffffffffu, se, o);
        sw += __shfl_xor_sync(0xffffffffu, sw, o);
    }
    if (lane == 0) { fin[warp] = sd; fin[8 + warp] = se; fin[16 + warp] = sw; }
    __syncthreads();
    if (t == 0) {
        float data_sum = 0.0f, ep_sum = 0.0f, wl_sum = 0.0f;
#pragma unroll
        for (int w = 0; w < 8; w++) {
            data_sum += fin[w];
            ep_sum += fin[8 + w];
            wl_sum += fin[16 + w];
        }
        float data_term = data_sum * (1.0f / (float)(B_N * M_N));
        float weighted_len = wl_sum / (ep_sum + 1e-8f);
        float sparsity = ep_sum * (1.0f / (float)(M_N * M_N));
        out[0] = data_term + LEN_C * weighted_len + SP_C * sparsity;
        // reset for next graph replay (next launch is stream-ordered after us)
        g_ctr = 0u;
        g_wtp_ready = 0u;
    }
}

// ---------------- launch ----------------
extern "C" void kernel_launch(void* const* d_in, const int* in_sizes, int n_in,
                              void* d_out, int out_size) {
    const float* data = (const float*)d_in[0];     // [4096, 256]
    const float* weights = (const float*)d_in[1];  // [256, 256]
    const float* elog = (const float*)d_in[2];     // [256, 256]
    float* out = (float*)d_out;

    k_produce<<<304, 256>>>(data, weights, elog);
    k_rank<<<B_N, 256>>>(out);
}

// round 12
// speedup vs baseline: 1.1107x; 1.1107x over previous
#include <cuda_runtime.h>
#include <cuda_bf16.h>
#include <math.h>

// Problem constants (fixed by setup_inputs)
#define B_N 4096
#define M_N 256
#define D_N 256

#define TAU_INV_LOG2E 7.213475204444817f   // log2(e)/0.2
#define LAM_INV_LOG2E 0.18033688011112043f // log2(e)/8
#define TOPO_C 0.5f
#define LEN_C 0.01f
#define SP_C 0.001f

typedef unsigned long long u64;

// ---------------- packed f32x2 helpers (sm_103a) ----------------
__device__ __forceinline__ u64 f2add(u64 a, u64 b) {
    u64 o; asm("add.rn.f32x2 %0, %1, %2;" : "=l"(o) : "l"(a), "l"(b)); return o;
}
__device__ __forceinline__ u64 f2mul(u64 a, u64 b) {
    u64 o; asm("mul.rn.f32x2 %0, %1, %2;" : "=l"(o) : "l"(a), "l"(b)); return o;
}
__device__ __forceinline__ u64 f2fma(u64 a, u64 b, u64 c) {
    u64 o; asm("fma.rn.f32x2 %0, %1, %2, %3;" : "=l"(o) : "l"(a), "l"(b), "l"(c)); return o;
}
__device__ __forceinline__ u64 f2dup(float x) {
    u64 o; asm("mov.b64 %0, {%1, %1};" : "=l"(o) : "f"(x)); return o;
}
__device__ __forceinline__ u64 f2pack(float x, float y) {
    u64 o; asm("mov.b64 %0, {%1, %2};" : "=l"(o) : "f"(x), "f"(y)); return o;
}
__device__ __forceinline__ float2 f2unpack(u64 v) {
    float2 o; asm("mov.b64 {%0, %1}, %2;" : "=f"(o.x), "=f"(o.y) : "l"(v)); return o;
}
__device__ __forceinline__ float frcp(float x) {
    float r; asm("rcp.approx.ftz.f32 %0, %1;" : "=f"(r) : "f"(x)); return r;
}

// ---------------- device scratch (no allocations allowed) ----------------
__device__ float g_Wtp[128 * 512];        // W transposed, k-pair-major: [k2][m][2], 256KB
__device__ float g_dist[B_N * M_N];       // 4 MB (L2-resident)
__device__ float g_dmax[B_N];             // per-row max distance
__device__ float g_wsq[M_N];
__device__ float g_factor[M_N];
__device__ float g_ep_rowsum[M_N];
__device__ float g_wl_rowsum[M_N];
__device__ float g_part[B_N];
__device__ unsigned int g_ctr = 0u;       // rank ticket (winner resets)

// ---------------- K1: W prep, 64 blocks x 128 threads (4 W rows each) ----------------
__global__ void __launch_bounds__(128) k_wprep(const float* __restrict__ W) {
    const int t = threadIdx.x;          // 0..127
    const int lane = t & 31, warp = t >> 5;
    const int m0 = blockIdx.x * 4;

    __shared__ __align__(16) float Ws[4][256];

    // load 4 rows: 256 float4 / 128 threads
#pragma unroll
    for (int p = 0; p < 2; p++) {
        int q = t + p * 128;            // 0..255
        int r = q >> 6, c4 = q & 63;
        *(float4*)&Ws[r][c4 * 4] = ((const float4*)W)[(size_t)(m0 + r) * 64 + c4];
    }
    __syncthreads();

    // wsq: warp w (0..3) reduces row w
    if (warp < 4) {
        float s = 0.0f;
#pragma unroll
        for (int p = 0; p < 8; p++) {
            float v = Ws[warp][lane + 32 * p];
            s = fmaf(v, v, s);
        }
#pragma unroll
        for (int o = 16; o; o >>= 1) s += __shfl_xor_sync(0xffffffffu, s, o);
        if (lane == 0) g_wsq[m0 + warp] = s;
    }

    // transpose: thread handles (k2, half) -> one contiguous float4 STG
    // Wtp[k2*512 + (m0+mloc)*2 + e] = Ws[mloc][2*k2+e]
#pragma unroll
    for (int p = 0; p < 2; p++) {
        int idx = t + p * 128;          // 0..255
        int k2 = idx >> 1, h = idx & 1; // k2 0..127, h = m-half
        float a0 = Ws[2 * h][2 * k2];
        float a1 = Ws[2 * h][2 * k2 + 1];
        float a2 = Ws[2 * h + 1][2 * k2];
        float a3 = Ws[2 * h + 1][2 * k2 + 1];
        *(float4*)&g_Wtp[k2 * 512 + m0 * 2 + h * 4] = make_float4(a0, a1, a2, a3);
    }
}

// ---------------- K2: mega = distance GEMM (blocks 0..255) + edges (blocks 256..319) ----------------
#define GR 16

__global__ void __launch_bounds__(128) k_mega(const float* __restrict__ X,
                                              const float* __restrict__ W,
                                              const float* __restrict__ E) {
    const int t = threadIdx.x;          // 0..127
    const int lane = t & 31, warp = t >> 5;

    __shared__ __align__(16) float Xs[GR][256];  // 16KB (edges branch aliases this)
    __shared__ __align__(16) float pool[8192];   // 32KB W chunk; later xsq/max scratch

    if (blockIdx.x < 256) {
        // ================= GEMM branch =================
        const int b0 = blockIdx.x * GR;
        const int m1 = t, m2 = t + 128;

        // load X tile: 1024 float4 / 128 threads
#pragma unroll
        for (int p = 0; p < 8; p++) {
            int q = t + p * 128;            // float4 idx 0..1023
            int r = q >> 6, c4 = q & 63;
            *(float4*)&Xs[r][c4 * 4] = ((const float4*)X)[(size_t)(b0 + r) * 64 + c4];
        }
        __syncthreads();

        u64 acc[GR][2];
#pragma unroll
        for (int r = 0; r < GR; r++) { acc[r][0] = 0ull; acc[r][1] = 0ull; }

        for (int chunk = 0; chunk < 8; chunk++) {
            const float4* src = (const float4*)(g_Wtp + chunk * 8192);
#pragma unroll
            for (int p = 0; p < 16; p++) {
                int idx = t + p * 128;
                ((float4*)pool)[idx] = src[idx];
            }
            __syncthreads();

#pragma unroll
            for (int k2 = 0; k2 < 16; k2 += 2) {
                u64 w0a = *(const u64*)&pool[k2 * 512 + m1 * 2];
                u64 w0b = *(const u64*)&pool[k2 * 512 + m2 * 2];
                u64 w1a = *(const u64*)&pool[(k2 + 1) * 512 + m1 * 2];
                u64 w1b = *(const u64*)&pool[(k2 + 1) * 512 + m2 * 2];
                int kg = (chunk * 16 + k2) * 2;     // 16B-aligned float idx
#pragma unroll
                for (int r = 0; r < GR; r++) {
                    ulonglong2 xv = *(const ulonglong2*)&Xs[r][kg];  // broadcast
                    acc[r][0] = f2fma(xv.x, w0a, acc[r][0]);
                    acc[r][1] = f2fma(xv.x, w0b, acc[r][1]);
                    acc[r][0] = f2fma(xv.y, w1a, acc[r][0]);
                    acc[r][1] = f2fma(xv.y, w1b, acc[r][1]);
                }
            }
            __syncthreads();
        }

        // xsq in-block: warp w reduces rows 4w..4w+3 from Xs; store into pool[0..15]
#pragma unroll
        for (int rr = 0; rr < 4; rr++) {
            int row = warp * 4 + rr;
            float s = 0.0f;
#pragma unroll
            for (int p = 0; p < 8; p++) {
                float v = Xs[row][lane + 32 * p];
                s = fmaf(v, v, s);
            }
#pragma unroll
            for (int o = 16; o; o >>= 1) s += __shfl_xor_sync(0xffffffffu, s, o);
            if (lane == 0) pool[row] = s;
        }
        __syncthreads();

        float wsq1 = g_wsq[m1], wsq2 = g_wsq[m2];
#pragma unroll
        for (int r = 0; r < GR; r++) {
            float xq = pool[r];
            float2 da = f2unpack(acc[r][0]);
            float2 db = f2unpack(acc[r][1]);
            float dot1 = da.x + da.y;
            float dot2 = db.x + db.y;
            float d1 = sqrtf(fmaxf(xq + wsq1 - 2.0f * dot1, 0.0f));
            float d2 = sqrtf(fmaxf(xq + wsq2 - 2.0f * dot2, 0.0f));
            g_dist[(size_t)(b0 + r) * M_N + m1] = d1;
            g_dist[(size_t)(b0 + r) * M_N + m2] = d2;
            // per-row max partials -> pool[64 + r*4 + warp]
            float mx = fmaxf(d1, d2);
#pragma unroll
            for (int o = 16; o; o >>= 1) mx = fmaxf(mx, __shfl_xor_sync(0xffffffffu, mx, o));
            if (lane == 0) pool[64 + r * 4 + warp] = mx;
        }
        __syncthreads();
        if (t < GR) {
            float m = pool[64 + t * 4];
#pragma unroll
            for (int w = 1; w < 4; w++) m = fmaxf(m, pool[64 + t * 4 + w]);
            g_dmax[b0 + t] = m;
        }
        return;
    }

    // ================= EDGES branch (128 threads, 2 j-columns each) =================
    {
        const int i0 = (blockIdx.x - 256) * 4;
        float* wis = &Xs[0][0];              // 4 rows x 256 floats
        float* red_ep = &Xs[8][0];           // [4][4]
        float* red_wl = &Xs[8][16];          // [4][4]

#pragma unroll
        for (int p = 0; p < 8; p++) {
            int q = t + p * 128;
            int r = q >> 8, k = q & 255;
            wis[r * 256 + k] = W[(size_t)(i0 + r) * D_N + k];
        }
        __syncthreads();

        u64 acc[4][2];
#pragma unroll
        for (int i = 0; i < 4; i++) { acc[i][0] = 0ull; acc[i][1] = 0ull; }

        const float* wtp1 = g_Wtp + t * 2;
        const float* wtp2 = g_Wtp + (t + 128) * 2;
#pragma unroll 4
        for (int k2 = 0; k2 < 128; k2++) {
            u64 wj1 = *(const u64*)(wtp1 + k2 * 512);
            u64 wj2 = *(const u64*)(wtp2 + k2 * 512);
#pragma unroll
            for (int i = 0; i < 4; i++) {
                u64 xw = *(const u64*)&wis[i * 256 + 2 * k2];
                acc[i][0] = f2fma(xw, wj1, acc[i][0]);
                acc[i][1] = f2fma(xw, wj2, acc[i][1]);
            }
        }

        float wsq1 = g_wsq[t], wsq2 = g_wsq[t + 128];
#pragma unroll
        for (int i = 0; i < 4; i++) {
            int ig = i0 + i;
            float wsqi = g_wsq[ig];
            float sep, swl;
            {
                float2 q1 = f2unpack(acc[i][0]);
                float dot1 = q1.x + q1.y;
                float pd1 = fmaxf(wsqi + wsq1 - 2.0f * dot1, 0.0f);
                float l1 = 0.5f * (E[ig * M_N + t] + E[t * M_N + ig]);
                float ep1 = __fdividef(1.0f, 1.0f + __expf(-l1));
                if (t == ig) ep1 = 0.0f;

                float2 q2 = f2unpack(acc[i][1]);
                float dot2 = q2.x + q2.y;
                float pd2 = fmaxf(wsqi + wsq2 - 2.0f * dot2, 0.0f);
                float l2 = 0.5f * (E[ig * M_N + (t + 128)] + E[(t + 128) * M_N + ig]);
                float ep2 = __fdividef(1.0f, 1.0f + __expf(-l2));
                if (t + 128 == ig) ep2 = 0.0f;

                sep = ep1 + ep2;
                swl = ep1 * pd1 + ep2 * pd2;
            }
#pragma unroll
            for (int o = 16; o; o >>= 1) {
                sep += __shfl_xor_sync(0xffffffffu, sep, o);
                swl += __shfl_xor_sync(0xffffffffu, swl, o);
            }
            if (lane == 0) { red_ep[i * 4 + warp] = sep; red_wl[i * 4 + warp] = swl; }
        }
        __syncthreads();
        if (t < 4) {
            float rs = 0.0f, rw = 0.0f;
#pragma unroll
            for (int w = 0; w < 4; w++) { rs += red_ep[t * 4 + w]; rw += red_wl[t * 4 + w]; }
            int ig = i0 + t;
            g_ep_rowsum[ig] = rs;
            g_wl_rowsum[ig] = rw;
            g_factor[ig] = 1.0f + TOPO_C * (rs / (float)(M_N - 1));
        }
    }
}

// ---------------- K3: soft-rank via quartic + synthetic-division derivative ----------------
__global__ void __launch_bounds__(256) k_rank(float* __restrict__ out) {
    const int b = blockIdx.x;
    const int t = threadIdx.x;
    const int lane = t & 31, warp = t >> 5;

    __shared__ __align__(16) float us[256];        // interleaved u table (128 u64 pairs)
    __shared__ __align__(16) ulonglong2 tbl[64];   // 32 groups x {e1,e2},{e3,e4}
    __shared__ float red[8];

    float d = g_dist[(size_t)b * M_N + t];
    float dmax = __ldg(&g_dmax[b]);

    // u table (rescaled by 2^30; ratio-invariant). P in [2^-120, 2^124]: safe.
    float arg = fmaxf((d - dmax) * TAU_INV_LOG2E, -60.0f) + 30.0f;
    float ui = exp2f(arg);
    us[2 * (t & 127) + (t >> 7)] = ui;   // u64 slot k = (u_k, u_{k+128})
    __syncthreads();

    // build per-group coefficient tables (32 groups of 4 packed u's)
    if (t < 32) {
        const u64* uv = (const u64*)us;
        u64 u0 = uv[4 * t], u1 = uv[4 * t + 1], u2 = uv[4 * t + 2], u3 = uv[4 * t + 3];
        u64 s01 = f2add(u0, u1), p01 = f2mul(u0, u1);
        u64 s23 = f2add(u2, u3), p23 = f2mul(u2, u3);
        ulonglong2 A, Bc;
        A.x = f2add(s01, s23);                       // e1
        A.y = f2fma(s01, s23, f2add(p01, p23));      // e2
        Bc.x = f2fma(p01, s23, f2mul(p23, s01));     // e3
        Bc.y = f2mul(p01, p23);                      // e4
        tbl[2 * t] = A; tbl[2 * t + 1] = Bc;
    }
    __syncthreads();

    const u64 ui2 = f2dup(ui);
    u64 acc = 0ull;
#pragma unroll 8
    for (int g = 0; g < 32; g++) {
        ulonglong2 A = tbl[2 * g];         // e1, e2
        ulonglong2 Bc = tbl[2 * g + 1];    // e3, e4
        // P Horner with intermediates
        u64 t1 = f2add(ui2, A.x);
        u64 t2 = f2fma(t1, ui2, A.y);
        u64 t3 = f2fma(t2, ui2, Bc.x);
        u64 P  = f2fma(t3, ui2, Bc.y);
        // P' = ((x + t1)x + t2)x + t3  (synthetic division)
        u64 q1 = f2add(ui2, t1);
        u64 q2 = f2fma(q1, ui2, t2);
        u64 Dv = f2fma(q2, ui2, t3);
        // rcp + accumulate P'/P
        float2 pu = f2unpack(P);
        u64 rr = f2pack(frcp(pu.x), frcp(pu.y));
        acc = f2fma(Dv, rr, acc);
    }
    float2 av = f2unpack(acc);
    float ssum = ui * (av.x + av.y);       // includes diagonal 0.5
    float neigh = exp2f(-(ssum - 0.5f) * LAM_INV_LOG2E);
    float contrib = neigh * d * g_factor[t];

#pragma unroll
    for (int o = 16; o; o >>= 1) contrib += __shfl_xor_sync(0xffffffffu, contrib, o);
    if (lane == 0) red[warp] = contrib;
    __syncthreads();
    if (t == 0) {
        float s = red[0];
#pragma unroll
        for (int w = 1; w < 8; w++) s += red[w];
        g_part[b] = s;
    }

    // ---- last block: final loss assembly + ticket reset for next replay ----
    __shared__ unsigned int ticket;
    __threadfence();
    __syncthreads();
    if (t == 0) ticket = atomicAdd(&g_ctr, 1u);
    __syncthreads();
    if (ticket != (unsigned int)(gridDim.x - 1)) return;

    __shared__ float fin[24];
    float sd = 0.0f;
    const float4* gp4 = (const float4*)g_part;
#pragma unroll
    for (int p = 0; p < 4; p++) {
        float4 v = gp4[t + 256 * p];
        sd += (v.x + v.y) + (v.z + v.w);
    }
    float se = g_ep_rowsum[t];
    float sw = g_wl_rowsum[t];
#pragma unroll
    for (int o = 16; o; o >>= 1) {
        sd += __shfl_xor_sync(0xffffffffu, sd, o);
        se += __shfl_xor_sync(0xffffffffu, se, o);
        sw += __shfl_xor_sync(0xffffffffu, sw, o);
    }
    if (lane == 0) { fin[warp] = sd; fin[8 + warp] = se; fin[16 + warp] = sw; }
    __syncthreads();
    if (t == 0) {
        float data_sum = 0.0f, ep_sum = 0.0f, wl_sum = 0.0f;
#pragma unroll
        for (int w = 0; w < 8; w++) {
            data_sum += fin[w];
            ep_sum += fin[8 + w];
            wl_sum += fin[16 + w];
        }
        float data_term = data_sum * (1.0f / (float)(B_N * M_N));
        float weighted_len = wl_sum / (ep_sum + 1e-8f);
        float sparsity = ep_sum * (1.0f / (float)(M_N * M_N));
        out[0] = data_term + LEN_C * weighted_len + SP_C * sparsity;
        g_ctr = 0u;   // clean for next graph replay
    }
}

// ---------------- launch ----------------
extern "C" void kernel_launch(void* const* d_in, const int* in_sizes, int n_in,
                              void* d_out, int out_size) {
    const float* data = (const float*)d_in[0];     // [4096, 256]
    const float* weights = (const float*)d_in[1];  // [256, 256]
    const float* elog = (const float*)d_in[2];     // [256, 256]
    float* out = (float*)d_out;

    k_wprep<<<64, 128>>>(weights);
    k_mega<<<320, 128>>>(data, weights, elog);
    k_rank<<<B_N, 256>>>(out);
}